// round 2
// baseline (speedup 1.0000x reference)
#include <cuda_runtime.h>
#include <cstdint>

#ifndef THRESH
#define THRESH 0.7f
#endif

// 4 slots per thread. All traffic as 128-bit streaming loads/stores.
// Output layout: [rects B*N*4][scores B*N][keep B*N]
__global__ void __launch_bounds__(256) rnet_post_kernel4(
    const float4* __restrict__ cls4,    // [total/2] : 2 slots per float4
    const float4* __restrict__ reg,     // [total]
    const float4* __restrict__ rects,   // [total]
    const int*    __restrict__ hptr,
    const int*    __restrict__ wptr,
    float4* __restrict__ out_rects,     // [total]
    float4* __restrict__ out_scores4,   // [total/4]
    float4* __restrict__ out_keep4,     // [total/4]
    int nquads)                         // total/4
{
    const float fh = (float)(*hptr);
    const float fw = (float)(*wptr);

    int i = blockIdx.x * blockDim.x + threadIdx.x;
    if (i >= nquads) return;

    // Front-batched loads: 2 cls + 4 reg + 4 rects = 10 LDG.128
    const float4 c0 = __ldcs(&cls4[2 * i]);
    const float4 c1 = __ldcs(&cls4[2 * i + 1]);
    float4 r[4], d[4];
#pragma unroll
    for (int k = 0; k < 4; k++) r[k] = __ldcs(&rects[4 * i + k]);
#pragma unroll
    for (int k = 0; k < 4; k++) d[k] = __ldcs(&reg[4 * i + k]);

    const float sc[4] = {c0.y, c0.w, c1.y, c1.w};
    float kp[4], so[4];
    float4 ro[4];
#pragma unroll
    for (int k = 0; k < 4; k++) {
        const float keep = (sc[k] > THRESH) ? 1.0f : 0.0f;
        kp[k] = keep;
        so[k] = sc[k] * keep;
        const float w = r[k].z - r[k].x;
        const float h = r[k].w - r[k].y;
        float nx1 = fminf(fmaxf(fmaf(d[k].x, w, r[k].x), 0.0f), fw);
        float ny1 = fminf(fmaxf(fmaf(d[k].y, h, r[k].y), 0.0f), fh);
        float nx2 = fminf(fmaxf(fmaf(d[k].z, w, r[k].z), 0.0f), fw);
        float ny2 = fminf(fmaxf(fmaf(d[k].w, h, r[k].w), 0.0f), fh);
        ro[k] = make_float4(nx1 * keep, ny1 * keep, nx2 * keep, ny2 * keep);
    }

#pragma unroll
    for (int k = 0; k < 4; k++) __stcs(&out_rects[4 * i + k], ro[k]);
    __stcs(&out_scores4[i], make_float4(so[0], so[1], so[2], so[3]));
    __stcs(&out_keep4[i],   make_float4(kp[0], kp[1], kp[2], kp[3]));
}

// Tail kernel for total % 4 != 0 (not expected for B*N = 4M, but safe).
__global__ void rnet_post_tail(
    const float2* __restrict__ cls,
    const float4* __restrict__ reg,
    const float4* __restrict__ rects,
    const int* __restrict__ hptr, const int* __restrict__ wptr,
    float4* __restrict__ out_rects, float* __restrict__ out_scores,
    float* __restrict__ out_keep, int start, int total)
{
    int i = start + blockIdx.x * blockDim.x + threadIdx.x;
    if (i >= total) return;
    const float fh = (float)(*hptr);
    const float fw = (float)(*wptr);
    const float2 c = cls[i];
    const float4 r = rects[i];
    const float4 d = reg[i];
    const float keep = (c.y > THRESH) ? 1.0f : 0.0f;
    const float w = r.z - r.x, h = r.w - r.y;
    float nx1 = fminf(fmaxf(fmaf(d.x, w, r.x), 0.0f), fw);
    float ny1 = fminf(fmaxf(fmaf(d.y, h, r.y), 0.0f), fh);
    float nx2 = fminf(fmaxf(fmaf(d.z, w, r.z), 0.0f), fw);
    float ny2 = fminf(fmaxf(fmaf(d.w, h, r.w), 0.0f), fh);
    out_rects[i]  = make_float4(nx1 * keep, ny1 * keep, nx2 * keep, ny2 * keep);
    out_scores[i] = c.y * keep;
    out_keep[i]   = keep;
}

extern "C" void kernel_launch(void* const* d_in, const int* in_sizes, int n_in,
                              void* d_out, int out_size)
{
    const float* cls    = (const float*)d_in[0];  // classifier [B,N,2]
    const float4* reg   = (const float4*)d_in[1];
    const float4* rects = (const float4*)d_in[2];
    const int*    hptr  = (const int*)d_in[3];
    const int*    wptr  = (const int*)d_in[4];

    const int total  = in_sizes[0] / 2;  // B*N
    const int nquads = total / 4;
    const int tail_start = nquads * 4;

    float* out         = (float*)d_out;
    float4* out_rects  = (float4*)out;
    float* out_scores  = out + (size_t)total * 4;
    float* out_keep    = out + (size_t)total * 5;

    const int threads = 256;
    if (nquads > 0) {
        const int blocks = (nquads + threads - 1) / threads;
        rnet_post_kernel4<<<blocks, threads>>>(
            (const float4*)cls, reg, rects, hptr, wptr,
            out_rects, (float4*)out_scores, (float4*)out_keep, nquads);
    }
    if (tail_start < total) {
        const int nt = total - tail_start;
        rnet_post_tail<<<(nt + threads - 1) / threads, threads>>>(
            (const float2*)cls, reg, rects, hptr, wptr,
            out_rects, out_scores, out_keep, tail_start, total);
    }
}

// round 3
// speedup vs baseline: 1.0417x; 1.0417x over previous
#include <cuda_runtime.h>
#include <cstdint>

#ifndef THRESH
#define THRESH 0.7f
#endif

// One thread per (b,n) slot (R1 structure) + streaming cache hints:
// the 268MB working set is touched exactly once, so mark all traffic
// evict-first to stop L2 thrash.
// Output layout: [rects B*N*4][scores B*N][keep B*N]
__global__ void __launch_bounds__(512) rnet_post_kernel(
    const float2* __restrict__ cls,    // [total] of (p0, p1)
    const float4* __restrict__ reg,    // [total] of (dx1,dy1,dx2,dy2)
    const float4* __restrict__ rects,  // [total] of (x1,y1,x2,y2)
    const int*    __restrict__ hptr,   // scalar H
    const int*    __restrict__ wptr,   // scalar W
    float4* __restrict__ out_rects,    // [total]
    float*  __restrict__ out_scores,   // [total]
    float*  __restrict__ out_keep,     // [total]
    int total)
{
    const float fh = (float)(*hptr);
    const float fw = (float)(*wptr);

    int i = blockIdx.x * blockDim.x + threadIdx.x;
    if (i >= total) return;

    const float2 c = __ldcs(&cls[i]);
    const float4 r = __ldcs(&rects[i]);
    const float4 d = __ldcs(&reg[i]);

    const float score = c.y;
    const float keep  = (score > THRESH) ? 1.0f : 0.0f;

    const float w = r.z - r.x;
    const float h = r.w - r.y;

    float nx1 = fminf(fmaxf(fmaf(d.x, w, r.x), 0.0f), fw);
    float ny1 = fminf(fmaxf(fmaf(d.y, h, r.y), 0.0f), fh);
    float nx2 = fminf(fmaxf(fmaf(d.z, w, r.z), 0.0f), fw);
    float ny2 = fminf(fmaxf(fmaf(d.w, h, r.w), 0.0f), fh);

    __stcs(&out_rects[i], make_float4(nx1 * keep, ny1 * keep, nx2 * keep, ny2 * keep));
    __stcs(&out_scores[i], score * keep);
    __stcs(&out_keep[i], keep);
}

extern "C" void kernel_launch(void* const* d_in, const int* in_sizes, int n_in,
                              void* d_out, int out_size)
{
    const float2* cls   = (const float2*)d_in[0];  // classifier [B,N,2]
    const float4* reg   = (const float4*)d_in[1];  // bbox_regress [B,N,4]
    const float4* rects = (const float4*)d_in[2];  // input_rects [B,N,4]
    const int*    hptr  = (const int*)d_in[3];     // input_height scalar
    const int*    wptr  = (const int*)d_in[4];     // input_width scalar

    const int total = in_sizes[0] / 2;             // B*N

    float* out        = (float*)d_out;
    float4* out_rects = (float4*)out;              // total * 4 floats
    float* out_scores = out + (size_t)total * 4;   // total floats
    float* out_keep   = out + (size_t)total * 5;   // total floats

    const int threads = 512;
    const int blocks  = (total + threads - 1) / threads;
    rnet_post_kernel<<<blocks, threads>>>(cls, reg, rects, hptr, wptr,
                                          out_rects, out_scores, out_keep, total);
}